// round 3
// baseline (speedup 1.0000x reference)
#include <cuda_runtime.h>
#include <math_constants.h>

#define NS     5000
#define SPTS   10
#define NSEG   9
#define KNN    20
#define HH     512
#define WW     512
#define HC     102
#define WC     102
#define NCELL  (HC*WC)

// ---------------- scratch (static device globals; no runtime allocation) ----
__device__ float4 g_seg[NS * NSEG];         // per segment: ax, ay, bx, by
__device__ float  g_d2[NS * NSEG];          // per segment: bx^2 + by^2 (ref rounding)
__device__ float4 g_bbox[NS];               // per stroke: cx, cy, ex, ey (AABB center/half-extent)
__device__ float4 g_colw[NS];               // rgb + width packed
__device__ int    g_tidx[NCELL * KNN];      // per coarse cell: sorted top-K stroke ids
__device__ float  g_tw[NCELL * KNN];        // per coarse cell: width of slot-k stroke

// ---------------- kernel 1: bezier points -> segments, bbox, color/width ----
// Matches XLA rounding on the amplified path: each op individually rounded,
// no FMA contraction. bbox is only a conservative cull bound (any rounding ok).
__global__ void k_bezier(const float* __restrict__ cs, const float* __restrict__ ce,
                         const float* __restrict__ cc, const float* __restrict__ color,
                         const float* __restrict__ loc, const float* __restrict__ width)
{
    int n = blockIdx.x * blockDim.x + threadIdx.x;
    if (n >= NS) return;
    float lx = loc[2*n], ly = loc[2*n+1];
    float Sx = __fadd_rn(cs[2*n],   lx), Sy = __fadd_rn(cs[2*n+1], ly);
    float Ex = __fadd_rn(ce[2*n],   lx), Ey = __fadd_rn(ce[2*n+1], ly);
    float Cx = __fadd_rn(cc[2*n],   lx), Cy = __fadd_rn(cc[2*n+1], ly);
    float dsx = __fsub_rn(Sx, Cx), dsy = __fsub_rn(Sy, Cy);
    float dex = __fsub_rn(Ex, Cx), dey = __fsub_rn(Ey, Cy);
    float step = __fdiv_rn(1.0f, 9.0f);
    float ptx[SPTS], pty[SPTS];
    float mnx = CUDART_INF_F, mxx = -CUDART_INF_F;
    float mny = CUDART_INF_F, mxy = -CUDART_INF_F;
    #pragma unroll
    for (int i = 0; i < SPTS; i++) {
        float t   = __fmul_rn((float)i, step);
        float omt = __fsub_rn(1.0f, t);
        float o2  = __fmul_rn(omt, omt);
        float t2  = __fmul_rn(t, t);
        float px = __fadd_rn(__fadd_rn(Cx, __fmul_rn(o2, dsx)), __fmul_rn(t2, dex));
        float py = __fadd_rn(__fadd_rn(Cy, __fmul_rn(o2, dsy)), __fmul_rn(t2, dey));
        ptx[i] = px; pty[i] = py;
        mnx = fminf(mnx, px); mxx = fmaxf(mxx, px);
        mny = fminf(mny, py); mxy = fmaxf(mxy, py);
    }
    #pragma unroll
    for (int s = 0; s < NSEG; s++) {
        float bx = __fsub_rn(ptx[s+1], ptx[s]);
        float by = __fsub_rn(pty[s+1], pty[s]);
        g_seg[n*NSEG + s] = make_float4(ptx[s], pty[s], bx, by);
        g_d2 [n*NSEG + s] = __fadd_rn(__fmul_rn(bx, bx), __fmul_rn(by, by));
    }
    g_bbox[n] = make_float4(0.5f*(mnx+mxx), 0.5f*(mny+mxy),
                            0.5f*(mxx-mnx) + 1e-3f, 0.5f*(mxy-mny) + 1e-3f);
    g_colw[n] = make_float4(color[3*n], color[3*n+1], color[3*n+2], width[n]);
}

// ---------------- kernel 2: coarse-grid top-K nearest strokes ---------------
// 4 threads per cell on strided stroke subsets; each keeps a (d,idx)-sorted
// top-K (strict '<' = stable ties), then a lexicographic 4-way merge exactly
// reproduces jax.lax.top_k ordering. Distances use reference rounding.
#define PARTS  4
#define CPB    32                 // cells per block (128 threads)
#define TILE2  1024
__global__ void __launch_bounds__(CPB*PARTS) k_topk(const float* __restrict__ loc,
                                                    const float* __restrict__ width)
{
    __shared__ float2 sl[TILE2];
    __shared__ float2 sml[CPB][PARTS][KNN];   // (d, idx-bits)

    int c    = threadIdx.x >> 2;              // local cell 0..31
    int part = threadIdx.x & 3;
    int cell = blockIdx.x * CPB + c;
    bool active = (cell < NCELL);
    float px = 0.f, py = 0.f;
    if (active) {
        int ci = cell / WC, cj = cell % WC;
        float step = __fdiv_rn(512.0f, 101.0f);   // linspace(0,512,102)
        px = __fmul_rn((float)ci, step);
        py = __fmul_rn((float)cj, step);
    }
    float bd[KNN]; int bi[KNN];
    #pragma unroll
    for (int k = 0; k < KNN; k++) { bd[k] = CUDART_INF_F; bi[k] = 0x7fffffff; }

    for (int base = 0; base < NS; base += TILE2) {
        int cnt = min(TILE2, NS - base);
        __syncthreads();
        for (int i = threadIdx.x; i < cnt; i += blockDim.x)
            sl[i] = ((const float2*)loc)[base + i];
        __syncthreads();
        if (active) {
            for (int i = part; i < cnt; i += PARTS) {
                float dx = __fsub_rn(px, sl[i].x);
                float dy = __fsub_rn(py, sl[i].y);
                float d  = __fadd_rn(__fmul_rn(dx, dx), __fmul_rn(dy, dy));
                if (d < bd[KNN-1]) {
                    int j = KNN - 1;
                    while (j > 0 && d < bd[j-1]) {
                        bd[j] = bd[j-1]; bi[j] = bi[j-1]; j--;
                    }
                    bd[j] = d; bi[j] = base + i;
                }
            }
        }
    }
    __syncthreads();
    #pragma unroll
    for (int k = 0; k < KNN; k++)
        sml[c][part][k] = make_float2(bd[k], __int_as_float(bi[k]));
    __syncthreads();

    if (active && part == 0) {
        int ptr[PARTS] = {0,0,0,0};
        for (int k = 0; k < KNN; k++) {
            float bestd = CUDART_INF_F; int besti = 0x7fffffff; int bestp = 0;
            #pragma unroll
            for (int p = 0; p < PARTS; p++) {
                if (ptr[p] < KNN) {
                    float2 v = sml[c][p][ptr[p]];
                    float d = v.x; int i = __float_as_int(v.y);
                    if (d < bestd || (d == bestd && i < besti)) {
                        bestd = d; besti = i; bestp = p;
                    }
                }
            }
            ptr[bestp]++;
            g_tidx[cell*KNN + k] = besti;
            g_tw  [cell*KNN + k] = __ldg(width + besti);
        }
    }
}

// ---------------- kernel 3: full-res shading with bit-exact culling ---------
// A stroke with r_ub = 1e5/(lb+1e-8) < M_cur - 1000 has (a) m_k > current min
// so it cannot change D, and (b) expf(r_k - M_cur) underflows to exactly 0.0f,
// so skipping it leaves the output bit-identical. lb is a conservative AABB
// distance lower bound (fast math fine). Top-K is nearest-first, so M is
// established at k=0 and most strokes cull.
__global__ void __launch_bounds__(256) k_render(float* __restrict__ out)
{
    int lane = threadIdx.x & 31;
    int wrp  = threadIdx.x >> 5;       // 0..7
    int subx = lane & 7, suby = lane >> 3;
    int wx = wrp & 1,  wy = wrp >> 1;
    int w = blockIdx.x * 16 + wx * 8 + subx;   // width index (second coord)
    int h = blockIdx.y * 16 + wy * 4 + suby;   // height index (first coord)

    float stepf = __fdiv_rn(512.0f, 511.0f);   // linspace(0,512,512)
    float pxf = __fmul_rn((float)h, stepf);
    float pyf = __fmul_rn((float)w, stepf);

    // nearest-upsample coarse cell (exact: 102/512 = 51/256 exact in f32)
    int ch = min((int)((float)h * 0.19921875f), HC - 1);
    int cw = min((int)((float)w * 0.19921875f), WC - 1);
    const int* idxp = g_tidx + (ch*WC + cw) * KNN;

    // half-pixel bilinear for the width resize (edge-clamped lerp ==
    // jax's renormalized triangle kernel at the borders); smooth path.
    float yc = ((float)h + 0.5f) * 0.19921875f - 0.5f;
    float xc = ((float)w + 0.5f) * 0.19921875f - 0.5f;
    float y0f = floorf(yc), x0f = floorf(xc);
    float fy = yc - y0f,    fx = xc - x0f;
    int y0 = max(0, min(HC-1, (int)y0f));
    int y1 = max(0, min(HC-1, (int)y0f + 1));
    int x0 = max(0, min(WC-1, (int)x0f));
    int x1 = max(0, min(WC-1, (int)x0f + 1));
    const float* pw00 = g_tw + (y0*WC + x0) * KNN;
    const float* pw01 = g_tw + (y0*WC + x1) * KNN;
    const float* pw10 = g_tw + (y1*WC + x0) * KNN;
    const float* pw11 = g_tw + (y1*WC + x1) * KNN;
    float c00 = (1.f-fy)*(1.f-fx), c01 = (1.f-fy)*fx;
    float c10 = fy*(1.f-fx),       c11 = fy*fx;

    float M = -CUDART_INF_F;
    float sum = 0.f, a0 = 0.f, a1 = 0.f, a2 = 0.f, bw = 0.f;
    float D = CUDART_INF_F;

    #pragma unroll
    for (int k = 0; k < KNN; k++) {
        int idx = __ldg(idxp + k);

        // conservative AABB distance^2 lower bound (cull test; fast math ok)
        float4 bb = __ldg(&g_bbox[idx]);
        float ddx = fmaxf(fabsf(pxf - bb.x) - bb.z, 0.0f);
        float ddy = fmaxf(fabsf(pyf - bb.y) - bb.w, 0.0f);
        float lb  = ddx*ddx + ddy*ddy;
        float r_ub = __fdividef(100000.0f, lb + 1e-8f);

        if (r_ub >= M - 1000.0f) {
            // m = min over segments of ||P - (a + t*b)||^2 with per-op
            // reference rounding (no fma, IEEE div).
            const float4* sp = g_seg + idx * NSEG;
            const float*  dp = g_d2  + idx * NSEG;
            float m = CUDART_INF_F;
            #pragma unroll
            for (int s = 0; s < NSEG; s++) {
                float4 sg = __ldg(sp + s);
                float d2  = __ldg(dp + s);
                float pax = __fsub_rn(pxf, sg.x);
                float pay = __fsub_rn(pyf, sg.y);
                float dot1 = __fadd_rn(__fmul_rn(sg.z, pax), __fmul_rn(sg.w, pay));
                float t = __fdiv_rn(dot1, d2);
                t = fminf(fmaxf(t, 0.0f), 1.0f);
                float cx = __fadd_rn(sg.x, __fmul_rn(t, sg.z));
                float cy = __fadd_rn(sg.y, __fmul_rn(t, sg.w));
                float dx = __fsub_rn(pxf, cx);
                float dy = __fsub_rn(pyf, cy);
                float d = __fadd_rn(__fmul_rn(dx, dx), __fmul_rn(dy, dy));
                m = fminf(m, d);
            }
            D = fminf(D, m);

            // r = 100000 * (1 / (1e-8 + m)) — reference rounding
            float r = __fmul_rn(100000.0f, __fdiv_rn(1.0f, __fadd_rn(1e-8f, m)));

            float wk = c00*__ldg(pw00+k) + c01*__ldg(pw01+k)
                     + c10*__ldg(pw10+k) + c11*__ldg(pw11+k);
            float4 col = __ldg(&g_colw[idx]);
            float e;
            if (r > M) {
                float sc = expf(M - r);   // exp(-inf)=0 on first iteration
                sum *= sc; a0 *= sc; a1 *= sc; a2 *= sc; bw *= sc;
                M = r; e = 1.0f;
            } else {
                e = expf(__fsub_rn(r, M));
            }
            sum += e;
            a0 += e * col.x; a1 += e * col.y; a2 += e * col.z;
            bw += e * wk;
        }
    }

    float inv  = __fdiv_rn(1.0f, sum);
    float bs   = bw * inv;
    // XLA lowers jax.nn.sigmoid (lax.logistic) as 0.5 + 0.5*tanh(0.5*x)
    float marg = __fmul_rn(0.5f, __fsub_rn(bs, D));
    float mask = __fadd_rn(0.5f, __fmul_rn(0.5f, tanhf(marg)));
    float om   = __fsub_rn(1.0f, mask);
    int o = (h * WW + w) * 3;
    out[o+0] = __fadd_rn(__fmul_rn(a0*inv, mask), __fmul_rn(om, 0.5f));
    out[o+1] = __fadd_rn(__fmul_rn(a1*inv, mask), __fmul_rn(om, 0.5f));
    out[o+2] = __fadd_rn(__fmul_rn(a2*inv, mask), __fmul_rn(om, 0.5f));
}

// ---------------- launch ----------------------------------------------------
extern "C" void kernel_launch(void* const* d_in, const int* in_sizes, int n_in,
                              void* d_out, int out_size)
{
    const float* curve_s  = (const float*)d_in[0];
    const float* curve_e  = (const float*)d_in[1];
    const float* curve_c  = (const float*)d_in[2];
    const float* color    = (const float*)d_in[3];
    const float* location = (const float*)d_in[4];
    const float* width    = (const float*)d_in[5];
    float* out = (float*)d_out;

    k_bezier<<<(NS + 255) / 256, 256>>>(curve_s, curve_e, curve_c, color, location, width);
    k_topk<<<(NCELL + CPB - 1) / CPB, CPB * PARTS>>>(location, width);
    dim3 grid(WW / 16, HH / 16);
    k_render<<<grid, 256>>>(out);
}

// round 4
// speedup vs baseline: 5.5954x; 5.5954x over previous
#include <cuda_runtime.h>
#include <math_constants.h>

#define NS     5000
#define SPTS   10
#define NSEG   9
#define KNN    20
#define HH     512
#define WW     512
#define HC     102
#define WC     102
#define NCELL  (HC*WC)

// ---------------- scratch (static device globals; no runtime allocation) ----
__device__ float4 g_seg[NS * NSEG];         // per segment: ax, ay, bx, by
__device__ float  g_d2[NS * NSEG];          // per segment: bx^2+by^2 (ref rounding)
__device__ float4 g_colw[NS];               // rgb + width packed
__device__ int    g_tidx[NCELL * KNN];      // per coarse cell: sorted top-K stroke ids
__device__ float  g_tw[NCELL * KNN];        // per coarse cell: width of slot-k stroke

// ---------------- kernel 1: bezier -> segments, color/width -----------------
// Amplified path ops individually rounded (no FMA), matching XLA.
__global__ void k_bezier(const float* __restrict__ cs, const float* __restrict__ ce,
                         const float* __restrict__ cc, const float* __restrict__ color,
                         const float* __restrict__ loc, const float* __restrict__ width)
{
    int n = blockIdx.x * blockDim.x + threadIdx.x;
    if (n >= NS) return;
    float lx = loc[2*n], ly = loc[2*n+1];
    float Sx = __fadd_rn(cs[2*n],   lx), Sy = __fadd_rn(cs[2*n+1], ly);
    float Ex = __fadd_rn(ce[2*n],   lx), Ey = __fadd_rn(ce[2*n+1], ly);
    float Cx = __fadd_rn(cc[2*n],   lx), Cy = __fadd_rn(cc[2*n+1], ly);
    float dsx = __fsub_rn(Sx, Cx), dsy = __fsub_rn(Sy, Cy);
    float dex = __fsub_rn(Ex, Cx), dey = __fsub_rn(Ey, Cy);
    float step = __fdiv_rn(1.0f, 9.0f);
    float ptx[SPTS], pty[SPTS];
    #pragma unroll
    for (int i = 0; i < SPTS; i++) {
        float t   = __fmul_rn((float)i, step);
        float omt = __fsub_rn(1.0f, t);
        float o2  = __fmul_rn(omt, omt);
        float t2  = __fmul_rn(t, t);
        ptx[i] = __fadd_rn(__fadd_rn(Cx, __fmul_rn(o2, dsx)), __fmul_rn(t2, dex));
        pty[i] = __fadd_rn(__fadd_rn(Cy, __fmul_rn(o2, dsy)), __fmul_rn(t2, dey));
    }
    #pragma unroll
    for (int s = 0; s < NSEG; s++) {
        float bx = __fsub_rn(ptx[s+1], ptx[s]);
        float by = __fsub_rn(pty[s+1], pty[s]);
        g_seg[n*NSEG + s] = make_float4(ptx[s], pty[s], bx, by);
        g_d2 [n*NSEG + s] = __fadd_rn(__fmul_rn(bx, bx), __fmul_rn(by, by));
    }
    g_colw[n] = make_float4(color[3*n], color[3*n+1], color[3*n+2], width[n]);
}

// ---------------- kernel 2: coarse-grid top-K nearest strokes ---------------
// 2 threads/cell on index-parity subsets. Each keeps a register-resident,
// ascending-sorted top-K via a branchless unrolled compare-swap chain (NO
// local memory). Strict '<' + ascending index scan + lexicographic 2-way merge
// reproduce jax.lax.top_k stable tie order exactly. Distances use the exact
// reference rounding (sub, mul, mul, add — no fma).
#define PARTS  2
#define CPB    64                 // cells per block (128 threads)
#define TILE2  1024
__global__ void __launch_bounds__(CPB*PARTS) k_topk(const float* __restrict__ loc,
                                                    const float* __restrict__ width)
{
    __shared__ float2 sl[TILE2];
    __shared__ float2 sml[CPB][PARTS][KNN];   // (d, idx-bits)

    int c    = threadIdx.x >> 1;              // local cell 0..63
    int part = threadIdx.x & 1;
    int cell = blockIdx.x * CPB + c;
    bool active = (cell < NCELL);
    float px = 0.f, py = 0.f;
    if (active) {
        int ci = cell / WC, cj = cell % WC;
        float step = __fdiv_rn(512.0f, 101.0f);   // linspace(0,512,102)
        px = __fmul_rn((float)ci, step);
        py = __fmul_rn((float)cj, step);
    }
    float bd[KNN]; int bi[KNN];
    #pragma unroll
    for (int k = 0; k < KNN; k++) { bd[k] = CUDART_INF_F; bi[k] = 0x7fffffff; }

    for (int base = 0; base < NS; base += TILE2) {
        int cnt = min(TILE2, NS - base);
        __syncthreads();
        for (int i = threadIdx.x; i < cnt; i += blockDim.x)
            sl[i] = ((const float2*)loc)[base + i];
        __syncthreads();
        if (active) {
            for (int i = part; i < cnt; i += PARTS) {
                float dx = __fsub_rn(px, sl[i].x);
                float dy = __fsub_rn(py, sl[i].y);
                float d  = __fadd_rn(__fmul_rn(dx, dx), __fmul_rn(dy, dy));
                if (d < bd[KNN-1]) {
                    float id = d; int ii = base + i;
                    #pragma unroll
                    for (int j = 0; j < KNN; j++) {
                        bool sw = id < bd[j];
                        float td = bd[j]; int ti = bi[j];
                        if (sw) { bd[j] = id; bi[j] = ii; id = td; ii = ti; }
                    }
                }
            }
        }
    }
    __syncthreads();
    #pragma unroll
    for (int k = 0; k < KNN; k++)
        sml[c][part][k] = make_float2(bd[k], __int_as_float(bi[k]));
    __syncthreads();

    if (active && part == 0) {
        int p0 = 0, p1 = 0;
        #pragma unroll
        for (int k = 0; k < KNN; k++) {
            float2 v0 = sml[c][0][p0];
            float2 v1 = sml[c][1][p1];
            float d0 = v0.x; int i0 = __float_as_int(v0.y);
            float d1 = v1.x; int i1 = __float_as_int(v1.y);
            bool take0 = (d0 < d1) || (d0 == d1 && i0 < i1);
            int besti = take0 ? i0 : i1;
            if (take0) p0++; else p1++;
            g_tidx[cell*KNN + k] = besti;
            g_tw  [cell*KNN + k] = __ldg(width + besti);
        }
    }
}

// ---------------- kernel 3: full-res shading (branchless, full ILP) ---------
// 256 threads/block; warp covers an 8x4 pixel tile so lanes mostly share a
// coarse cell (L1 broadcast of stroke data). The amplified path (segment
// distance -> r) replicates XLA per-op rounding exactly. The softmax/blend
// path is smooth (errors not amplified) -> fast exp/div are safe.
__global__ void __launch_bounds__(256, 2) k_render(float* __restrict__ out)
{
    int lane = threadIdx.x & 31;
    int wrp  = threadIdx.x >> 5;       // 0..7
    int subx = lane & 7, suby = lane >> 3;
    int wx = wrp & 1,  wy = wrp >> 1;
    int w = blockIdx.x * 16 + wx * 8 + subx;   // width index (second coord)
    int h = blockIdx.y * 16 + wy * 4 + suby;   // height index (first coord)

    float stepf = __fdiv_rn(512.0f, 511.0f);   // linspace(0,512,512)
    float pxf = __fmul_rn((float)h, stepf);
    float pyf = __fmul_rn((float)w, stepf);

    // nearest-upsample coarse cell (exact: 102/512 = 51/256 exact in f32)
    int ch = min((int)((float)h * 0.19921875f), HC - 1);
    int cw = min((int)((float)w * 0.19921875f), WC - 1);
    const int* idxp = g_tidx + (ch*WC + cw) * KNN;

    // half-pixel bilinear for the width resize (edge-clamped lerp ==
    // jax's renormalized triangle kernel at the borders); smooth path.
    float yc = ((float)h + 0.5f) * 0.19921875f - 0.5f;
    float xc = ((float)w + 0.5f) * 0.19921875f - 0.5f;
    float y0f = floorf(yc), x0f = floorf(xc);
    float fy = yc - y0f,    fx = xc - x0f;
    int y0 = max(0, min(HC-1, (int)y0f));
    int y1 = max(0, min(HC-1, (int)y0f + 1));
    int x0 = max(0, min(WC-1, (int)x0f));
    int x1 = max(0, min(WC-1, (int)x0f + 1));
    const float* pw00 = g_tw + (y0*WC + x0) * KNN;
    const float* pw01 = g_tw + (y0*WC + x1) * KNN;
    const float* pw10 = g_tw + (y1*WC + x0) * KNN;
    const float* pw11 = g_tw + (y1*WC + x1) * KNN;
    float c00 = (1.f-fy)*(1.f-fx), c01 = (1.f-fy)*fx;
    float c10 = fy*(1.f-fx),       c11 = fy*fx;

    float M = -CUDART_INF_F;
    float sum = 0.f, a0 = 0.f, a1 = 0.f, a2 = 0.f, bw = 0.f;
    float D = CUDART_INF_F;

    #pragma unroll 2
    for (int k = 0; k < KNN; k++) {
        int idx = __ldg(idxp + k);

        // m = min over 9 segments of ||P - (a + t*b)||^2, per-op reference
        // rounding (no fma, IEEE div). Segments are independent -> ILP.
        const float4* sp = g_seg + idx * NSEG;
        const float*  dp = g_d2  + idx * NSEG;
        float m = CUDART_INF_F;
        #pragma unroll
        for (int s = 0; s < NSEG; s++) {
            float4 sg = __ldg(sp + s);
            float d2  = __ldg(dp + s);
            float pax = __fsub_rn(pxf, sg.x);
            float pay = __fsub_rn(pyf, sg.y);
            float dot1 = __fadd_rn(__fmul_rn(sg.z, pax), __fmul_rn(sg.w, pay));
            float t = __fdiv_rn(dot1, d2);
            t = fminf(fmaxf(t, 0.0f), 1.0f);
            float cx = __fadd_rn(sg.x, __fmul_rn(t, sg.z));
            float cy = __fadd_rn(sg.y, __fmul_rn(t, sg.w));
            float dx = __fsub_rn(pxf, cx);
            float dy = __fsub_rn(pyf, cy);
            float d = __fadd_rn(__fmul_rn(dx, dx), __fmul_rn(dy, dy));
            m = fminf(m, d);
        }
        D = fminf(D, m);

        // r = 100000 * (1 / (1e-8 + m)) — reference rounding (amplified)
        float r = __fmul_rn(100000.0f, __fdiv_rn(1.0f, __fadd_rn(1e-8f, m)));

        float wk = c00*__ldg(pw00+k) + c01*__ldg(pw01+k)
                 + c10*__ldg(pw10+k) + c11*__ldg(pw11+k);
        float4 col = __ldg(&g_colw[idx]);

        // branchless online softmax (exp output feeds linear blends only;
        // fast exp error ~1e-6 is not amplified)
        float newM = fmaxf(r, M);
        float sc = __expf(M - newM);   // M=-inf first iter -> 0
        float e  = __expf(r - newM);
        sum = sum*sc + e;
        a0  = a0 *sc + e*col.x;
        a1  = a1 *sc + e*col.y;
        a2  = a2 *sc + e*col.z;
        bw  = bw *sc + e*wk;
        M = newM;
    }

    float inv  = __fdividef(1.0f, sum);
    float bs   = bw * inv;
    float mask = __fdividef(1.0f, 1.0f + __expf(-(bs - D)));
    float om   = 1.0f - mask;
    int o = (h * WW + w) * 3;
    out[o+0] = a0*inv*mask + om*0.5f;
    out[o+1] = a1*inv*mask + om*0.5f;
    out[o+2] = a2*inv*mask + om*0.5f;
}

// ---------------- launch ----------------------------------------------------
extern "C" void kernel_launch(void* const* d_in, const int* in_sizes, int n_in,
                              void* d_out, int out_size)
{
    const float* curve_s  = (const float*)d_in[0];
    const float* curve_e  = (const float*)d_in[1];
    const float* curve_c  = (const float*)d_in[2];
    const float* color    = (const float*)d_in[3];
    const float* location = (const float*)d_in[4];
    const float* width    = (const float*)d_in[5];
    float* out = (float*)d_out;

    k_bezier<<<(NS + 255) / 256, 256>>>(curve_s, curve_e, curve_c, color, location, width);
    k_topk<<<(NCELL + CPB - 1) / CPB, CPB * PARTS>>>(location, width);
    dim3 grid(WW / 16, HH / 16);
    k_render<<<grid, 256>>>(out);
}